// round 4
// baseline (speedup 1.0000x reference)
#include <cuda_runtime.h>
#include <math.h>
#include <stdint.h>

// ---------------- scratch (no allocations allowed) ----------------
#define NGMAX   4096        // max local genes
#define NCUTMAX 1000000     // max cuts
#define NCGMAX  2048000     // max n_cells * n_genes

__device__ int    d_hist[NGMAX];
__device__ int    d_start[NGMAX + 1];
__device__ int    d_cursor[NGMAX];
__device__ int    d_order[NCUTMAX];
__device__ int    d_counts[NCGMAX];
__device__ float4 d_prm[NGMAX * 32];     // per (local gene, comp): {loc, 1/scale, log(scale), logit_w}
__device__ float  d_rwT[64 * NGMAX];     // gathered+transposed rho_weight: [l][g]
__device__ float  d_rbg[NGMAX];          // gathered rho_bias
__device__ double d_acc;                 // elbo accumulator (likelihood sum)

// ---------------- kernels ----------------

__global__ void k_zero(int ncg, int ng) {
    int i = blockIdx.x * blockDim.x + threadIdx.x;
    int stride = gridDim.x * blockDim.x;
    for (int j = i; j < ncg; j += stride) d_counts[j] = 0;
    for (int j = i; j < ng;  j += stride) d_hist[j] = 0;
    if (i == 0) d_acc = 0.0;
}

// Precompute gathered per-gene parameter tables (accurate transcendentals, off critical path)
__global__ void k_prep(const int* __restrict__ genes_oi,
                       const float* __restrict__ loc_w,
                       const float* __restrict__ scale_w,
                       const float* __restrict__ logit_w,
                       const float* __restrict__ rho_weight,
                       const float* __restrict__ rho_bias,
                       int ng) {
    int i = blockIdx.x * blockDim.x + threadIdx.x;
    int stride = gridDim.x * blockDim.x;
    for (int j = i; j < ng * 32; j += stride) {
        int g = j >> 5, c = j & 31;
        int gene = genes_oi[g];
        float lwv = logit_w[gene * 32 + c];
        float loc = 1.0f / (1.0f + expf(-loc_w[gene * 32 + c]));
        float sc  = 1e-5f + expf(scale_w[gene * 32 + c]);
        d_prm[j] = make_float4(loc, 1.0f / sc, logf(sc), lwv);
    }
    for (int j = i; j < ng * 64; j += stride) {
        int g = j % ng, l = j / ng;
        d_rwT[l * ng + g] = rho_weight[(size_t)genes_oi[g] * 64 + l];
    }
    for (int j = i; j < ng; j += stride) d_rbg[j] = rho_bias[genes_oi[j]];
}

// Histogram of cut genes (smem-privatized) + fragment counts histogram
__global__ void k_hist(const int* __restrict__ clcg,
                       const int* __restrict__ lcg,
                       int n_cuts, int n_frags, int ng) {
    __shared__ int sh[NGMAX];
    for (int i = threadIdx.x; i < ng; i += blockDim.x) sh[i] = 0;
    __syncthreads();
    int i0 = blockIdx.x * blockDim.x + threadIdx.x;
    int stride = gridDim.x * blockDim.x;
    for (int k = i0; k < n_cuts; k += stride) {
        int g = clcg[k] % ng;
        atomicAdd(&sh[g], 1);
    }
    __syncthreads();
    for (int i = threadIdx.x; i < ng; i += blockDim.x)
        if (sh[i]) atomicAdd(&d_hist[i], sh[i]);
    // fragment count histogram (spread over ~2M bins -> low contention)
    for (int f = i0; f < n_frags; f += stride)
        atomicAdd(&d_counts[lcg[f]], 1);
}

// Exclusive scan over gene histogram (single block, 1024 threads x 4 elems)
__global__ void k_scan(int ng) {
    __shared__ int tsum[1024];
    int t = threadIdx.x;
    int v[4];
    int base = t * 4;
    int s = 0;
#pragma unroll
    for (int j = 0; j < 4; j++) {
        int idx = base + j;
        v[j] = (idx < ng) ? d_hist[idx] : 0;
        s += v[j];
    }
    tsum[t] = s;
    __syncthreads();
    for (int off = 1; off < 1024; off <<= 1) {
        int x = (t >= off) ? tsum[t - off] : 0;
        __syncthreads();
        tsum[t] += x;
        __syncthreads();
    }
    int excl = tsum[t] - s;
#pragma unroll
    for (int j = 0; j < 4; j++) {
        int idx = base + j;
        if (idx < ng) {
            d_start[idx]  = excl;
            d_cursor[idx] = excl;
            excl += v[j];
        }
    }
    if (t == 1023) d_start[ng] = tsum[1023];
}

// Scatter cut indices into gene-grouped order
__global__ void k_scatter(const int* __restrict__ clcg, int n_cuts, int ng) {
    int i0 = blockIdx.x * blockDim.x + threadIdx.x;
    int stride = gridDim.x * blockDim.x;
    for (int k = i0; k < n_cuts; k += stride) {
        int g = clcg[k] % ng;
        int p = atomicAdd(&d_cursor[g], 1);
        d_order[p] = k;
    }
}

// Mixture log-likelihood: one CTA per local gene; weight row cached in SMEM;
// one warp per cut, lane = mixture component.
__global__ void __launch_bounds__(256) k_mix(
        const int* __restrict__ clcg,
        const float* __restrict__ coords,
        const float* __restrict__ latent,
        const int* __restrict__ genes_oi,
        const int* __restrict__ clg,
        const float* __restrict__ logit_weight,
        int ng) {
    __shared__ float lw_s[2048];   // [l][c], 64 x 32
    __shared__ float wpart[8];
    int g = blockIdx.x;
    int gene = genes_oi[g];
    const float* lwg = logit_weight + (size_t)gene * 2048;
    for (int i = threadIdx.x; i < 2048; i += blockDim.x) lw_s[i] = lwg[i];
    int s0 = d_start[g], s1 = d_start[g + 1];
    __syncthreads();

    int lane = threadIdx.x & 31;
    int w = threadIdx.x >> 5;
    float acc = 0.0f;

    for (int i = s0 + w; i < s1; i += 8) {
        int k  = d_order[i];                 // uniform across warp
        int ix = clcg[k];
        int cell = ix / ng;
        float r0 = latent[cell * 64 + lane];
        float r1 = latent[cell * 64 + 32 + lane];

        float a0 = 0.f, a1 = 0.f, a2 = 0.f, a3 = 0.f;
#pragma unroll
        for (int l = 0; l < 32; l += 4) {
            a0 = fmaf(__shfl_sync(0xffffffffu, r0, l + 0), lw_s[(l + 0) * 32 + lane], a0);
            a1 = fmaf(__shfl_sync(0xffffffffu, r0, l + 1), lw_s[(l + 1) * 32 + lane], a1);
            a2 = fmaf(__shfl_sync(0xffffffffu, r0, l + 2), lw_s[(l + 2) * 32 + lane], a2);
            a3 = fmaf(__shfl_sync(0xffffffffu, r0, l + 3), lw_s[(l + 3) * 32 + lane], a3);
        }
#pragma unroll
        for (int l = 0; l < 32; l += 4) {
            a0 = fmaf(__shfl_sync(0xffffffffu, r1, l + 0), lw_s[(32 + l + 0) * 32 + lane], a0);
            a1 = fmaf(__shfl_sync(0xffffffffu, r1, l + 1), lw_s[(32 + l + 1) * 32 + lane], a1);
            a2 = fmaf(__shfl_sync(0xffffffffu, r1, l + 2), lw_s[(32 + l + 2) * 32 + lane], a2);
            a3 = fmaf(__shfl_sync(0xffffffffu, r1, l + 3), lw_s[(32 + l + 3) * 32 + lane], a3);
        }
        float delta = (a0 + a1) + (a2 + a3);

        int g2 = clg[k];
        float4 p = d_prm[g2 * 32 + lane];    // {loc, inv_scale, log_scale, logit_w}
        float x = coords[k];
        float z = (x - p.x) * p.y;
        // comp_lp = -0.5 z^2 - log(scale) - 0.5*log(2*pi)
        float clp = fmaf(-0.5f * z, z, -p.z - 0.91893853320467274f);
        float la = p.w + delta;              // logits
        float lb = la + clp;

        // warp logsumexp over 32 components, twice
        float ma = la, mb = lb;
#pragma unroll
        for (int o = 16; o > 0; o >>= 1) {
            ma = fmaxf(ma, __shfl_xor_sync(0xffffffffu, ma, o));
            mb = fmaxf(mb, __shfl_xor_sync(0xffffffffu, mb, o));
        }
        float ea = expf(la - ma);
        float eb = expf(lb - mb);
#pragma unroll
        for (int o = 16; o > 0; o >>= 1) {
            ea += __shfl_xor_sync(0xffffffffu, ea, o);
            eb += __shfl_xor_sync(0xffffffffu, eb, o);
        }
        // lm = lse(logits+clp) - lse(logits)
        acc += (mb - ma) + (logf(eb) - logf(ea));
    }

    if (lane == 0) wpart[w] = acc;
    __syncthreads();
    if (threadIdx.x == 0) {
        float b = 0.f;
#pragma unroll
        for (int i = 0; i < 8; i++) b += wpart[i];
        atomicAdd(&d_acc, (double)b);
    }
}

// Fragment-count Poisson likelihood: one CTA per cell, coalesced over genes.
__global__ void __launch_bounds__(256) k_frag(
        const float* __restrict__ latent,
        const float* __restrict__ libsize,
        const int* __restrict__ cells_oi,
        int ng) {
    __shared__ float lat_s[64];
    __shared__ float wpart[8];
    int cell = blockIdx.x;
    if (threadIdx.x < 64) lat_s[threadIdx.x] = latent[cell * 64 + threadIdx.x];
    __syncthreads();
    float lib = libsize[cells_oi[cell]];
    float acc = 0.0f;

    for (int gg = threadIdx.x; gg < ng; gg += blockDim.x) {
        float r0 = 0.f, r1 = 0.f, r2 = 0.f, r3 = 0.f;
        const float* col = d_rwT + gg;
#pragma unroll
        for (int l = 0; l < 64; l += 4) {
            r0 = fmaf(lat_s[l + 0], col[(l + 0) * ng], r0);
            r1 = fmaf(lat_s[l + 1], col[(l + 1) * ng], r1);
            r2 = fmaf(lat_s[l + 2], col[(l + 2) * ng], r2);
            r3 = fmaf(lat_s[l + 3], col[(l + 3) * ng], r3);
        }
        float rho = (r0 + r1) + (r2 + r3);
        float fe = d_rbg[gg] * expf(rho) * lib;
        int c = d_counts[cell * ng + gg];
        float lf = -fe;
        if (c > 0)
            lf += (float)c * logf(fe) - lgammaf((float)c + 1.0f);
        acc += lf;
    }

    // block reduce
#pragma unroll
    for (int o = 16; o > 0; o >>= 1) acc += __shfl_xor_sync(0xffffffffu, acc, o);
    int lane = threadIdx.x & 31, w = threadIdx.x >> 5;
    if (lane == 0) wpart[w] = acc;
    __syncthreads();
    if (threadIdx.x == 0) {
        float b = 0.f;
#pragma unroll
        for (int i = 0; i < 8; i++) b += wpart[i];
        atomicAdd(&d_acc, (double)b);
    }
}

__global__ void k_final(float* out) {
    if (threadIdx.x == 0) out[0] = (float)(-d_acc);
}

// ---------------- launch ----------------
extern "C" void kernel_launch(void* const* d_in, const int* in_sizes, int n_in,
                              void* d_out, int out_size) {
    const int*   lcg      = (const int*)d_in[0];    // local_cellxgene_ix [n_frags]
    const float* coords   = (const float*)d_in[1];  // cut_coordinates [n_cuts]
    const float* latent   = (const float*)d_in[2];  // [n_cells, 64]
    const int*   genes_oi = (const int*)d_in[3];    // [n_genes]
    const int*   cells_oi = (const int*)d_in[4];    // [n_cells]
    const int*   clcg     = (const int*)d_in[5];    // cut_local_cellxgene_ix [n_cuts]
    const int*   clg      = (const int*)d_in[6];    // cut_local_gene_ix [n_cuts]
    // d_in[7], d_in[8] = n_cells, n_genes scalars (derived from sizes instead)
    const float* loc_w    = (const float*)d_in[9];
    const float* scale_w  = (const float*)d_in[10];
    const float* logit_w  = (const float*)d_in[11];
    const float* lw       = (const float*)d_in[12]; // logit_weight [20000,64,32]
    const float* rw       = (const float*)d_in[13]; // rho_weight [20000,64]
    const float* rho_bias = (const float*)d_in[14];
    const float* libsize  = (const float*)d_in[15];

    int n_frags = in_sizes[0];
    int n_cuts  = in_sizes[1];
    int n_cells = in_sizes[2] / 64;
    int n_genes = in_sizes[3];
    int ncg = n_cells * n_genes;

    float* out = (float*)d_out;
    (void)n_in; (void)out_size;

    k_zero<<<256, 256>>>(ncg, n_genes);
    k_prep<<<256, 256>>>(genes_oi, loc_w, scale_w, logit_w, rw, rho_bias, n_genes);
    k_hist<<<148, 512>>>(clcg, lcg, n_cuts, n_frags, n_genes);
    k_scan<<<1, 1024>>>(n_genes);
    k_scatter<<<256, 256>>>(clcg, n_cuts, n_genes);
    k_mix<<<n_genes, 256>>>(clcg, coords, latent, genes_oi, clg, lw, n_genes);
    k_frag<<<n_cells, 256>>>(latent, libsize, cells_oi, n_genes);
    k_final<<<1, 32>>>(out);
}

// round 5
// speedup vs baseline: 1.6731x; 1.6731x over previous
#include <cuda_runtime.h>
#include <math.h>
#include <stdint.h>

// ---------------- scratch (no allocations allowed) ----------------
#define NGMAX   4096        // max local genes
#define NCUTMAX 1000000     // max cuts
#define NCGMAX  2048000     // max n_cells * n_genes

__device__ int    d_hist[NGMAX];
__device__ int    d_start[NGMAX + 1];
__device__ int    d_cursor[NGMAX];
__device__ int2   d_info[NCUTMAX];       // sorted-by-gene: {cell | (g2<<16), coord bits}
__device__ int    d_counts[NCGMAX];
__device__ float4 d_prm[NGMAX * 32];     // per (local gene, comp): {loc, 1/scale, -log(scale)-0.5*log(2pi), logit_w}
__device__ float  d_rwT[64 * NGMAX];     // gathered+transposed rho_weight: [l][g]
__device__ float  d_rbg[NGMAX];          // gathered rho_bias
__device__ double d_acc;                 // likelihood accumulator

// ---------------- kernels ----------------

__global__ void k_zero(int ncg, int ng) {
    int i = blockIdx.x * blockDim.x + threadIdx.x;
    int stride = gridDim.x * blockDim.x;
    int ncg4 = ncg >> 2;
    int4* c4 = (int4*)d_counts;
    int4 z4 = make_int4(0, 0, 0, 0);
    for (int j = i; j < ncg4; j += stride) c4[j] = z4;
    for (int j = (ncg4 << 2) + i; j < ncg; j += stride) d_counts[j] = 0;
    for (int j = i; j < ng; j += stride) d_hist[j] = 0;
    if (i == 0) d_acc = 0.0;
}

// Precompute gathered per-gene parameter tables (accurate transcendentals, off critical path)
__global__ void k_prep(const int* __restrict__ genes_oi,
                       const float* __restrict__ loc_w,
                       const float* __restrict__ scale_w,
                       const float* __restrict__ logit_w,
                       const float* __restrict__ rho_weight,
                       const float* __restrict__ rho_bias,
                       int ng) {
    int i = blockIdx.x * blockDim.x + threadIdx.x;
    int stride = gridDim.x * blockDim.x;
    for (int j = i; j < ng * 32; j += stride) {
        int g = j >> 5, c = j & 31;
        int gene = genes_oi[g];
        float lwv = logit_w[gene * 32 + c];
        float loc = 1.0f / (1.0f + expf(-loc_w[gene * 32 + c]));
        float sc  = 1e-5f + expf(scale_w[gene * 32 + c]);
        // p.z = -log(scale) - 0.5*log(2*pi)  (folded constant)
        d_prm[j] = make_float4(loc, 1.0f / sc, -logf(sc) - 0.91893853320467274f, lwv);
    }
    for (int j = i; j < ng * 64; j += stride) {
        int g = j % ng, l = j / ng;
        d_rwT[l * ng + g] = rho_weight[(size_t)genes_oi[g] * 64 + l];
    }
    for (int j = i; j < ng; j += stride) d_rbg[j] = rho_bias[genes_oi[j]];
}

// Histogram of cut genes (smem-privatized) + fragment counts histogram
__global__ void k_hist(const int* __restrict__ clcg,
                       const int* __restrict__ lcg,
                       int n_cuts, int n_frags, int ng) {
    __shared__ int sh[NGMAX];
    for (int i = threadIdx.x; i < ng; i += blockDim.x) sh[i] = 0;
    __syncthreads();
    int i0 = blockIdx.x * blockDim.x + threadIdx.x;
    int stride = gridDim.x * blockDim.x;
    for (int k = i0; k < n_cuts; k += stride) {
        int g = clcg[k] % ng;
        atomicAdd(&sh[g], 1);
    }
    __syncthreads();
    for (int i = threadIdx.x; i < ng; i += blockDim.x)
        if (sh[i]) atomicAdd(&d_hist[i], sh[i]);
    // fragment count histogram (spread over ~2M bins -> low contention)
    for (int f = i0; f < n_frags; f += stride)
        atomicAdd(&d_counts[lcg[f]], 1);
}

// Exclusive scan over gene histogram (single block, 1024 threads x 4 elems)
__global__ void k_scan(int ng) {
    __shared__ int tsum[1024];
    int t = threadIdx.x;
    int v[4];
    int base = t * 4;
    int s = 0;
#pragma unroll
    for (int j = 0; j < 4; j++) {
        int idx = base + j;
        v[j] = (idx < ng) ? d_hist[idx] : 0;
        s += v[j];
    }
    tsum[t] = s;
    __syncthreads();
    for (int off = 1; off < 1024; off <<= 1) {
        int x = (t >= off) ? tsum[t - off] : 0;
        __syncthreads();
        tsum[t] += x;
        __syncthreads();
    }
    int excl = tsum[t] - s;
#pragma unroll
    for (int j = 0; j < 4; j++) {
        int idx = base + j;
        if (idx < ng) {
            d_start[idx]  = excl;
            d_cursor[idx] = excl;
            excl += v[j];
        }
    }
    if (t == 1023) d_start[ng] = tsum[1023];
}

// Scatter cuts into gene-grouped order, emitting packed per-cut info:
// {cell | (g2 << 16), coord-as-bits}
__global__ void k_scatter(const int* __restrict__ clcg,
                          const int* __restrict__ clg,
                          const float* __restrict__ coords,
                          int n_cuts, int ng) {
    int i0 = blockIdx.x * blockDim.x + threadIdx.x;
    int stride = gridDim.x * blockDim.x;
    for (int k = i0; k < n_cuts; k += stride) {
        int v = clcg[k];
        int g = v % ng;
        int cell = v / ng;
        int p = atomicAdd(&d_cursor[g], 1);
        d_info[p] = make_int2(cell | (clg[k] << 16), __float_as_int(coords[k]));
    }
}

// Mixture log-likelihood: one CTA per local gene.
// Lane c holds the gene's 64-long weight column for component c packed as
// 32 x f32x2 in registers. Each warp stages its cut's latent row into a
// private smem slot and reads it back as 16 uniform LDS.128 -> f32x2 FMAs.
__global__ void __launch_bounds__(256, 2) k_mix(
        const float* __restrict__ latent,
        const int* __restrict__ genes_oi,
        const float* __restrict__ logit_weight,
        int ng) {
    __shared__ float lat_s[2][8][64];   // [buf][warp][l]  (4 KB)
    __shared__ float wpart[8];
    int g = blockIdx.x;
    int lane = threadIdx.x & 31;
    int w = threadIdx.x >> 5;

    const float* lwg = logit_weight + (size_t)genes_oi[g] * 2048;
    unsigned long long w2[32];          // w2[m] = {lw[2m][lane], lw[2m+1][lane]}
#pragma unroll
    for (int m = 0; m < 32; m++) {
        float a = lwg[(2 * m) * 32 + lane];
        float b = lwg[(2 * m + 1) * 32 + lane];
        asm("mov.b64 %0, {%1, %2};" : "=l"(w2[m]) : "f"(a), "f"(b));
    }
    int s0 = d_start[g], s1 = d_start[g + 1];

    float acc = 0.0f;
    int buf = 0;
    for (int i = s0 + w; i < s1; i += 8, buf ^= 1) {
        int2 info = d_info[i];                    // uniform across warp
        int cell = info.x & 0xffff;
        int g2 = info.x >> 16;
        float x = __int_as_float(info.y);

        // stage latent row (coalesced 2x128B load, 2 STS)
        lat_s[buf][w][lane]      = latent[cell * 64 + lane];
        lat_s[buf][w][32 + lane] = latent[cell * 64 + 32 + lane];
        float4 p = d_prm[g2 * 32 + lane];         // lane-coalesced LDG.128
        __syncwarp();

        const ulonglong2* L = (const ulonglong2*)lat_s[buf][w];
        unsigned long long a0 = 0ULL, a1 = 0ULL;
#pragma unroll
        for (int j = 0; j < 16; j += 2) {
            ulonglong2 q = L[j];
            asm("fma.rn.f32x2 %0, %1, %2, %0;" : "+l"(a0) : "l"(q.x), "l"(w2[2 * j]));
            asm("fma.rn.f32x2 %0, %1, %2, %0;" : "+l"(a1) : "l"(q.y), "l"(w2[2 * j + 1]));
            ulonglong2 r = L[j + 1];
            asm("fma.rn.f32x2 %0, %1, %2, %0;" : "+l"(a0) : "l"(r.x), "l"(w2[2 * j + 2]));
            asm("fma.rn.f32x2 %0, %1, %2, %0;" : "+l"(a1) : "l"(r.y), "l"(w2[2 * j + 3]));
        }
        asm("add.rn.f32x2 %0, %0, %1;" : "+l"(a0) : "l"(a1));
        float dlo, dhi;
        asm("mov.b64 {%0, %1}, %2;" : "=f"(dlo), "=f"(dhi) : "l"(a0));
        float delta = dlo + dhi;

        float la = p.w + delta;                       // logits (|la| < ~10)
        float z = (x - p.x) * p.y;
        float lb = fmaf(-0.5f * z, z, la + p.z);      // la + comp_lp  (lb in [~-40, ~12])
        float ea = __expf(la);
        float eb = __expf(lb);
#pragma unroll
        for (int o = 16; o > 0; o >>= 1) {
            ea += __shfl_xor_sync(0xffffffffu, ea, o);
            eb += __shfl_xor_sync(0xffffffffu, eb, o);
        }
        // lm = lse(logits+clp) - lse(logits); no max needed (ranges bounded)
        acc += __logf(eb) - __logf(ea);
    }

    if (lane == 0) wpart[w] = acc;   // acc identical across lanes after butterflies
    __syncthreads();
    if (threadIdx.x == 0) {
        float b = 0.f;
#pragma unroll
        for (int i = 0; i < 8; i++) b += wpart[i];
        atomicAdd(&d_acc, (double)b);
    }
}

// Fragment-count Poisson likelihood: 4 cells per CTA (reuses rwT reads 4x),
// float4-vectorized over genes.
#define CPB 4
__global__ void __launch_bounds__(256) k_frag(
        const float* __restrict__ latent,
        const float* __restrict__ libsize,
        const int* __restrict__ cells_oi,
        int n_cells, int ng) {
    __shared__ float lat_s[CPB * 64];
    __shared__ float wpart[8];
    int c0 = blockIdx.x * CPB;
    int nc = min(CPB, n_cells - c0);
    for (int i = threadIdx.x; i < CPB * 64; i += blockDim.x)
        lat_s[i] = (i < nc * 64) ? latent[c0 * 64 + i] : 0.0f;
    __syncthreads();
    float lib[CPB];
#pragma unroll
    for (int j = 0; j < CPB; j++)
        lib[j] = (j < nc) ? libsize[cells_oi[c0 + j]] : 1.0f;

    float acc = 0.0f;
    int ngv = ng & ~3;
    for (int gg = threadIdx.x * 4; gg < ngv; gg += blockDim.x * 4) {
        float4 r[CPB];
#pragma unroll
        for (int j = 0; j < CPB; j++) r[j] = make_float4(0.f, 0.f, 0.f, 0.f);
#pragma unroll 8
        for (int l = 0; l < 64; l++) {
            float4 wv = *(const float4*)(d_rwT + l * ng + gg);
#pragma unroll
            for (int j = 0; j < CPB; j++) {
                float lv = lat_s[j * 64 + l];
                r[j].x = fmaf(lv, wv.x, r[j].x);
                r[j].y = fmaf(lv, wv.y, r[j].y);
                r[j].z = fmaf(lv, wv.z, r[j].z);
                r[j].w = fmaf(lv, wv.w, r[j].w);
            }
        }
        float4 rb = *(const float4*)(d_rbg + gg);
#pragma unroll
        for (int j = 0; j < CPB; j++) {
            if (j >= nc) break;
            int4 cnt = *(const int4*)(d_counts + (size_t)(c0 + j) * ng + gg);
            float fe, lf;
            fe = rb.x * __expf(r[j].x) * lib[j]; lf = -fe;
            if (cnt.x) lf += (float)cnt.x * __logf(fe) - lgammaf((float)cnt.x + 1.0f);
            acc += lf;
            fe = rb.y * __expf(r[j].y) * lib[j]; lf = -fe;
            if (cnt.y) lf += (float)cnt.y * __logf(fe) - lgammaf((float)cnt.y + 1.0f);
            acc += lf;
            fe = rb.z * __expf(r[j].z) * lib[j]; lf = -fe;
            if (cnt.z) lf += (float)cnt.z * __logf(fe) - lgammaf((float)cnt.z + 1.0f);
            acc += lf;
            fe = rb.w * __expf(r[j].w) * lib[j]; lf = -fe;
            if (cnt.w) lf += (float)cnt.w * __logf(fe) - lgammaf((float)cnt.w + 1.0f);
            acc += lf;
        }
    }
    // scalar tail genes
    for (int gg = ngv + threadIdx.x; gg < ng; gg += blockDim.x) {
        for (int j = 0; j < nc; j++) {
            float rho = 0.f;
            for (int l = 0; l < 64; l++)
                rho = fmaf(lat_s[j * 64 + l], d_rwT[l * ng + gg], rho);
            float fe = d_rbg[gg] * __expf(rho) * lib[j];
            int c = d_counts[(size_t)(c0 + j) * ng + gg];
            float lf = -fe;
            if (c) lf += (float)c * __logf(fe) - lgammaf((float)c + 1.0f);
            acc += lf;
        }
    }

#pragma unroll
    for (int o = 16; o > 0; o >>= 1) acc += __shfl_xor_sync(0xffffffffu, acc, o);
    int lane = threadIdx.x & 31, w = threadIdx.x >> 5;
    if (lane == 0) wpart[w] = acc;
    __syncthreads();
    if (threadIdx.x == 0) {
        float b = 0.f;
#pragma unroll
        for (int i = 0; i < 8; i++) b += wpart[i];
        atomicAdd(&d_acc, (double)b);
    }
}

__global__ void k_final(float* out) {
    if (threadIdx.x == 0) out[0] = (float)(-d_acc);
}

// ---------------- launch ----------------
extern "C" void kernel_launch(void* const* d_in, const int* in_sizes, int n_in,
                              void* d_out, int out_size) {
    const int*   lcg      = (const int*)d_in[0];    // local_cellxgene_ix [n_frags]
    const float* coords   = (const float*)d_in[1];  // cut_coordinates [n_cuts]
    const float* latent   = (const float*)d_in[2];  // [n_cells, 64]
    const int*   genes_oi = (const int*)d_in[3];    // [n_genes]
    const int*   cells_oi = (const int*)d_in[4];    // [n_cells]
    const int*   clcg     = (const int*)d_in[5];    // cut_local_cellxgene_ix [n_cuts]
    const int*   clg      = (const int*)d_in[6];    // cut_local_gene_ix [n_cuts]
    // d_in[7], d_in[8] = n_cells, n_genes scalars (derived from sizes instead)
    const float* loc_w    = (const float*)d_in[9];
    const float* scale_w  = (const float*)d_in[10];
    const float* logit_w  = (const float*)d_in[11];
    const float* lw       = (const float*)d_in[12]; // logit_weight [20000,64,32]
    const float* rw       = (const float*)d_in[13]; // rho_weight [20000,64]
    const float* rho_bias = (const float*)d_in[14];
    const float* libsize  = (const float*)d_in[15];

    int n_frags = in_sizes[0];
    int n_cuts  = in_sizes[1];
    int n_cells = in_sizes[2] / 64;
    int n_genes = in_sizes[3];
    int ncg = n_cells * n_genes;

    float* out = (float*)d_out;
    (void)n_in; (void)out_size;

    k_zero<<<256, 256>>>(ncg, n_genes);
    k_prep<<<256, 256>>>(genes_oi, loc_w, scale_w, logit_w, rw, rho_bias, n_genes);
    k_hist<<<148, 512>>>(clcg, lcg, n_cuts, n_frags, n_genes);
    k_scan<<<1, 1024>>>(n_genes);
    k_scatter<<<256, 256>>>(clcg, clg, coords, n_cuts, n_genes);
    k_mix<<<n_genes, 256>>>(latent, genes_oi, lw, n_genes);
    k_frag<<<(n_cells + CPB - 1) / CPB, 256>>>(latent, libsize, cells_oi, n_cells, n_genes);
    k_final<<<1, 32>>>(out);
}

// round 6
// speedup vs baseline: 2.1688x; 1.2963x over previous
#include <cuda_runtime.h>
#include <math.h>
#include <stdint.h>

// ---------------- scratch (no allocations allowed) ----------------
#define NGMAX   4096        // max local genes
#define NCUTMAX 1000000     // max cuts
#define NCGMAX  2048000     // max n_cells * n_genes

__device__ int    d_hist[NGMAX];
__device__ int    d_start[NGMAX + 1];
__device__ int    d_cursor[NGMAX];
__device__ int2   d_info[NCUTMAX];       // sorted-by-gene: {cell | (g2<<16), coord bits}
__device__ int    d_counts[NCGMAX];
__device__ float4 d_prm[NGMAX * 32];     // per (local gene, comp): {loc, 1/scale, -log(scale)-0.5*log(2pi), logit_w}
__device__ float  d_rwT[64 * NGMAX];     // gathered+transposed rho_weight: [l][g]
__device__ float  d_rbg[NGMAX];          // gathered rho_bias
__device__ double d_acc;                 // likelihood accumulator

// ---------------- kernels ----------------

__global__ void k_zero(int ncg, int ng) {
    int i = blockIdx.x * blockDim.x + threadIdx.x;
    int stride = gridDim.x * blockDim.x;
    int ncg4 = ncg >> 2;
    int4* c4 = (int4*)d_counts;
    int4 z4 = make_int4(0, 0, 0, 0);
    for (int j = i; j < ncg4; j += stride) c4[j] = z4;
    for (int j = (ncg4 << 2) + i; j < ncg; j += stride) d_counts[j] = 0;
    for (int j = i; j < ng; j += stride) d_hist[j] = 0;
    if (i == 0) d_acc = 0.0;
}

// Precompute gathered per-gene parameter tables (accurate transcendentals, off critical path)
__global__ void k_prep(const int* __restrict__ genes_oi,
                       const float* __restrict__ loc_w,
                       const float* __restrict__ scale_w,
                       const float* __restrict__ logit_w,
                       const float* __restrict__ rho_weight,
                       const float* __restrict__ rho_bias,
                       int ng) {
    int i = blockIdx.x * blockDim.x + threadIdx.x;
    int stride = gridDim.x * blockDim.x;
    for (int j = i; j < ng * 32; j += stride) {
        int g = j >> 5, c = j & 31;
        int gene = genes_oi[g];
        float lwv = logit_w[gene * 32 + c];
        float loc = 1.0f / (1.0f + expf(-loc_w[gene * 32 + c]));
        float sc  = 1e-5f + expf(scale_w[gene * 32 + c]);
        // p.z = -log(scale) - 0.5*log(2*pi)  (folded constant)
        d_prm[j] = make_float4(loc, 1.0f / sc, -logf(sc) - 0.91893853320467274f, lwv);
    }
    for (int j = i; j < ng * 64; j += stride) {
        int g = j % ng, l = j / ng;
        d_rwT[l * ng + g] = rho_weight[(size_t)genes_oi[g] * 64 + l];
    }
    for (int j = i; j < ng; j += stride) d_rbg[j] = rho_bias[genes_oi[j]];
}

// Histogram of cut genes (smem-privatized) + fragment counts histogram
__global__ void k_hist(const int* __restrict__ clcg,
                       const int* __restrict__ lcg,
                       int n_cuts, int n_frags, int ng) {
    __shared__ int sh[NGMAX];
    for (int i = threadIdx.x; i < ng; i += blockDim.x) sh[i] = 0;
    __syncthreads();
    int i0 = blockIdx.x * blockDim.x + threadIdx.x;
    int stride = gridDim.x * blockDim.x;
    for (int k = i0; k < n_cuts; k += stride) {
        int g = clcg[k] % ng;
        atomicAdd(&sh[g], 1);
    }
    __syncthreads();
    for (int i = threadIdx.x; i < ng; i += blockDim.x)
        if (sh[i]) atomicAdd(&d_hist[i], sh[i]);
    // fragment count histogram (spread over ~2M bins -> low contention)
    for (int f = i0; f < n_frags; f += stride)
        atomicAdd(&d_counts[lcg[f]], 1);
}

// Exclusive scan over gene histogram (single block, 1024 threads x 4 elems)
__global__ void k_scan(int ng) {
    __shared__ int tsum[1024];
    int t = threadIdx.x;
    int v[4];
    int base = t * 4;
    int s = 0;
#pragma unroll
    for (int j = 0; j < 4; j++) {
        int idx = base + j;
        v[j] = (idx < ng) ? d_hist[idx] : 0;
        s += v[j];
    }
    tsum[t] = s;
    __syncthreads();
    for (int off = 1; off < 1024; off <<= 1) {
        int x = (t >= off) ? tsum[t - off] : 0;
        __syncthreads();
        tsum[t] += x;
        __syncthreads();
    }
    int excl = tsum[t] - s;
#pragma unroll
    for (int j = 0; j < 4; j++) {
        int idx = base + j;
        if (idx < ng) {
            d_start[idx]  = excl;
            d_cursor[idx] = excl;
            excl += v[j];
        }
    }
    if (t == 1023) d_start[ng] = tsum[1023];
}

// Scatter cuts into gene-grouped order, emitting packed per-cut info:
// {cell | (g2 << 16), coord-as-bits}
__global__ void k_scatter(const int* __restrict__ clcg,
                          const int* __restrict__ clg,
                          const float* __restrict__ coords,
                          int n_cuts, int ng) {
    int i0 = blockIdx.x * blockDim.x + threadIdx.x;
    int stride = gridDim.x * blockDim.x;
    for (int k = i0; k < n_cuts; k += stride) {
        int v = clcg[k];
        int g = v % ng;
        int cell = v / ng;
        int p = atomicAdd(&d_cursor[g], 1);
        d_info[p] = make_int2(cell | (clg[k] << 16), __float_as_int(coords[k]));
    }
}

// Mixture log-likelihood: one CTA per local gene.
// Lane c holds the gene's 64-long weight column for component c packed as
// 32 x f32x2 in registers. Per-gene cut headers are block-staged into SMEM;
// each warp software-pipelines (depth 1) the latent/prm loads of cut j+8
// behind the compute of cut j, so no global-memory latency sits on the
// per-cut dependence chain.
#define CHUNK 512
__global__ void __launch_bounds__(256, 2) k_mix(
        const float* __restrict__ latent,
        const int* __restrict__ genes_oi,
        const float* __restrict__ logit_weight,
        int ng) {
    __shared__ int2  info_s[CHUNK];     // 4 KB
    __shared__ float lat_s[2][8][64];   // [buf][warp][l]  (4 KB)
    __shared__ float wpart[8];
    int g = blockIdx.x;
    int lane = threadIdx.x & 31;
    int w = threadIdx.x >> 5;

    const float* lwg = logit_weight + (size_t)genes_oi[g] * 2048;
    unsigned long long w2[32];          // w2[m] = {lw[2m][lane], lw[2m+1][lane]}
#pragma unroll
    for (int m = 0; m < 32; m++) {
        float a = lwg[(2 * m) * 32 + lane];
        float b = lwg[(2 * m + 1) * 32 + lane];
        asm("mov.b64 %0, {%1, %2};" : "=l"(w2[m]) : "f"(a), "f"(b));
    }
    int s0 = d_start[g], s1 = d_start[g + 1];
    float acc = 0.0f;

    for (int base = s0; base < s1; base += CHUNK) {
        int n = min(CHUNK, s1 - base);
        __syncthreads();   // previous chunk fully consumed
        for (int t = threadIdx.x; t < n; t += 256)
            info_s[t] = d_info[base + t];
        __syncthreads();

        int j = w;
        int buf = 0;
        float4 pc;
        float xc;
        if (j < n) {   // prologue: load cut j
            int2 ic = info_s[j];
            int cellc = ic.x & 0xffff;
            xc = __int_as_float(ic.y);
            pc = d_prm[(ic.x >> 16) * 32 + lane];
            lat_s[0][w][lane]      = latent[cellc * 64 + lane];
            lat_s[0][w][32 + lane] = latent[cellc * 64 + 32 + lane];
        }
        for (; j < n; j += 8) {
            // ---- prefetch cut j+8 (loads overlap the compute below) ----
            int jn = j + 8;
            bool has = jn < n;
            float4 pn;
            float xn = 0.f, ln0 = 0.f, ln1 = 0.f;
            if (has) {
                int2 in2 = info_s[jn];
                int celln = in2.x & 0xffff;
                xn = __int_as_float(in2.y);
                ln0 = latent[celln * 64 + lane];
                ln1 = latent[celln * 64 + 32 + lane];
                pn = d_prm[(in2.x >> 16) * 32 + lane];
            }
            __syncwarp();   // make previous iteration's STS (this buf) visible

            // ---- compute cut j from lat_s[buf] ----
            const ulonglong2* L = (const ulonglong2*)lat_s[buf][w];
            unsigned long long a0 = 0ULL, a1 = 0ULL, a2 = 0ULL, a3 = 0ULL;
#pragma unroll
            for (int q = 0; q < 16; q += 2) {
                ulonglong2 u = L[q];
                asm("fma.rn.f32x2 %0, %1, %2, %0;" : "+l"(a0) : "l"(u.x), "l"(w2[2 * q]));
                asm("fma.rn.f32x2 %0, %1, %2, %0;" : "+l"(a1) : "l"(u.y), "l"(w2[2 * q + 1]));
                ulonglong2 v = L[q + 1];
                asm("fma.rn.f32x2 %0, %1, %2, %0;" : "+l"(a2) : "l"(v.x), "l"(w2[2 * q + 2]));
                asm("fma.rn.f32x2 %0, %1, %2, %0;" : "+l"(a3) : "l"(v.y), "l"(w2[2 * q + 3]));
            }
            asm("add.rn.f32x2 %0, %0, %1;" : "+l"(a0) : "l"(a1));
            asm("add.rn.f32x2 %0, %0, %1;" : "+l"(a2) : "l"(a3));
            asm("add.rn.f32x2 %0, %0, %1;" : "+l"(a0) : "l"(a2));
            float dlo, dhi;
            asm("mov.b64 {%0, %1}, %2;" : "=f"(dlo), "=f"(dhi) : "l"(a0));
            float delta = dlo + dhi;

            float la = pc.w + delta;                       // logits (|la| < ~10)
            float z = (xc - pc.x) * pc.y;
            float lb = fmaf(-0.5f * z, z, la + pc.z);      // la + comp_lp (bounded)
            float ea = __expf(la);
            float eb = __expf(lb);
#pragma unroll
            for (int o = 16; o > 0; o >>= 1) {
                ea += __shfl_xor_sync(0xffffffffu, ea, o);
                eb += __shfl_xor_sync(0xffffffffu, eb, o);
            }
            // lm = lse(logits+clp) - lse(logits); no max needed (ranges bounded)
            acc += __logf(eb) - __logf(ea);

            // ---- commit prefetch into the other buffer ----
            if (has) {
                lat_s[buf ^ 1][w][lane]      = ln0;
                lat_s[buf ^ 1][w][32 + lane] = ln1;
                pc = pn;
                xc = xn;
            }
            buf ^= 1;
        }
    }

    if (lane == 0) wpart[w] = acc;   // acc identical across lanes after butterflies
    __syncthreads();
    if (threadIdx.x == 0) {
        float b = 0.f;
#pragma unroll
        for (int i = 0; i < 8; i++) b += wpart[i];
        atomicAdd(&d_acc, (double)b);
    }
}

// Fragment-count Poisson likelihood: 4 cells per CTA (reuses rwT reads 4x),
// float4-vectorized over genes; lgamma via small-count SMEM table.
#define CPB 4
__global__ void __launch_bounds__(256) k_frag(
        const float* __restrict__ latent,
        const float* __restrict__ libsize,
        const int* __restrict__ cells_oi,
        int n_cells, int ng) {
    __shared__ float lat_s[CPB * 64];
    __shared__ float lgam[32];          // lgam[c] = lgamma(c+1) = log(c!)
    __shared__ float wpart[8];
    int c0 = blockIdx.x * CPB;
    int nc = min(CPB, n_cells - c0);
    if (threadIdx.x < 32) lgam[threadIdx.x] = lgammaf((float)threadIdx.x + 1.0f);
    for (int i = threadIdx.x; i < CPB * 64; i += blockDim.x)
        lat_s[i] = (i < nc * 64) ? latent[c0 * 64 + i] : 0.0f;
    __syncthreads();
    float lib[CPB];
#pragma unroll
    for (int j = 0; j < CPB; j++)
        lib[j] = (j < nc) ? libsize[cells_oi[c0 + j]] : 1.0f;

    float acc = 0.0f;
    int ngv = ng & ~3;
    for (int gg = threadIdx.x * 4; gg < ngv; gg += blockDim.x * 4) {
        float4 r[CPB];
#pragma unroll
        for (int j = 0; j < CPB; j++) r[j] = make_float4(0.f, 0.f, 0.f, 0.f);
#pragma unroll 8
        for (int l = 0; l < 64; l++) {
            float4 wv = *(const float4*)(d_rwT + l * ng + gg);
#pragma unroll
            for (int j = 0; j < CPB; j++) {
                float lv = lat_s[j * 64 + l];
                r[j].x = fmaf(lv, wv.x, r[j].x);
                r[j].y = fmaf(lv, wv.y, r[j].y);
                r[j].z = fmaf(lv, wv.z, r[j].z);
                r[j].w = fmaf(lv, wv.w, r[j].w);
            }
        }
        float4 rb = *(const float4*)(d_rbg + gg);
#pragma unroll
        for (int j = 0; j < CPB; j++) {
            if (j >= nc) break;
            int4 cnt = *(const int4*)(d_counts + (size_t)(c0 + j) * ng + gg);
            float fe, lf;
            fe = rb.x * __expf(r[j].x) * lib[j]; lf = -fe;
            if (cnt.x) lf += (float)cnt.x * __logf(fe) - (cnt.x < 32 ? lgam[cnt.x] : lgammaf((float)cnt.x + 1.0f));
            acc += lf;
            fe = rb.y * __expf(r[j].y) * lib[j]; lf = -fe;
            if (cnt.y) lf += (float)cnt.y * __logf(fe) - (cnt.y < 32 ? lgam[cnt.y] : lgammaf((float)cnt.y + 1.0f));
            acc += lf;
            fe = rb.z * __expf(r[j].z) * lib[j]; lf = -fe;
            if (cnt.z) lf += (float)cnt.z * __logf(fe) - (cnt.z < 32 ? lgam[cnt.z] : lgammaf((float)cnt.z + 1.0f));
            acc += lf;
            fe = rb.w * __expf(r[j].w) * lib[j]; lf = -fe;
            if (cnt.w) lf += (float)cnt.w * __logf(fe) - (cnt.w < 32 ? lgam[cnt.w] : lgammaf((float)cnt.w + 1.0f));
            acc += lf;
        }
    }
    // scalar tail genes
    for (int gg = ngv + threadIdx.x; gg < ng; gg += blockDim.x) {
        for (int j = 0; j < nc; j++) {
            float rho = 0.f;
            for (int l = 0; l < 64; l++)
                rho = fmaf(lat_s[j * 64 + l], d_rwT[l * ng + gg], rho);
            float fe = d_rbg[gg] * __expf(rho) * lib[j];
            int c = d_counts[(size_t)(c0 + j) * ng + gg];
            float lf = -fe;
            if (c) lf += (float)c * __logf(fe) - (c < 32 ? lgam[c] : lgammaf((float)c + 1.0f));
            acc += lf;
        }
    }

#pragma unroll
    for (int o = 16; o > 0; o >>= 1) acc += __shfl_xor_sync(0xffffffffu, acc, o);
    int lane = threadIdx.x & 31, w = threadIdx.x >> 5;
    if (lane == 0) wpart[w] = acc;
    __syncthreads();
    if (threadIdx.x == 0) {
        float b = 0.f;
#pragma unroll
        for (int i = 0; i < 8; i++) b += wpart[i];
        atomicAdd(&d_acc, (double)b);
    }
}

__global__ void k_final(float* out) {
    if (threadIdx.x == 0) out[0] = (float)(-d_acc);
}

// ---------------- launch ----------------
extern "C" void kernel_launch(void* const* d_in, const int* in_sizes, int n_in,
                              void* d_out, int out_size) {
    const int*   lcg      = (const int*)d_in[0];    // local_cellxgene_ix [n_frags]
    const float* coords   = (const float*)d_in[1];  // cut_coordinates [n_cuts]
    const float* latent   = (const float*)d_in[2];  // [n_cells, 64]
    const int*   genes_oi = (const int*)d_in[3];    // [n_genes]
    const int*   cells_oi = (const int*)d_in[4];    // [n_cells]
    const int*   clcg     = (const int*)d_in[5];    // cut_local_cellxgene_ix [n_cuts]
    const int*   clg      = (const int*)d_in[6];    // cut_local_gene_ix [n_cuts]
    // d_in[7], d_in[8] = n_cells, n_genes scalars (derived from sizes instead)
    const float* loc_w    = (const float*)d_in[9];
    const float* scale_w  = (const float*)d_in[10];
    const float* logit_w  = (const float*)d_in[11];
    const float* lw       = (const float*)d_in[12]; // logit_weight [20000,64,32]
    const float* rw       = (const float*)d_in[13]; // rho_weight [20000,64]
    const float* rho_bias = (const float*)d_in[14];
    const float* libsize  = (const float*)d_in[15];

    int n_frags = in_sizes[0];
    int n_cuts  = in_sizes[1];
    int n_cells = in_sizes[2] / 64;
    int n_genes = in_sizes[3];
    int ncg = n_cells * n_genes;

    float* out = (float*)d_out;
    (void)n_in; (void)out_size;

    k_zero<<<256, 256>>>(ncg, n_genes);
    k_prep<<<256, 256>>>(genes_oi, loc_w, scale_w, logit_w, rw, rho_bias, n_genes);
    k_hist<<<148, 512>>>(clcg, lcg, n_cuts, n_frags, n_genes);
    k_scan<<<1, 1024>>>(n_genes);
    k_scatter<<<256, 256>>>(clcg, clg, coords, n_cuts, n_genes);
    k_mix<<<n_genes, 256>>>(latent, genes_oi, lw, n_genes);
    k_frag<<<(n_cells + CPB - 1) / CPB, 256>>>(latent, libsize, cells_oi, n_cells, n_genes);
    k_final<<<1, 32>>>(out);
}